// round 1
// baseline (speedup 1.0000x reference)
#include <cuda_runtime.h>
#include <cstdint>

// Problem constants (fixed by reference setup)
#define B_    32
#define L_    50
#define C_    80
#define R_TOT 14175   // 60*60*3 + 30*30*3 + 15*15*3
#define NPART 56736   // 1350*32 + 338*32 + 85*32

// Precomputed GT records (SoA of float4, per (b,l)):
//  q0 = {x, y, area(=w*h), int_as_float(valid ? best_anchor : -1)}
//  q1 = {xmin, ymin, xmax, ymax}   (normalized)
//  q2 = {tw=log(w/aw), th=log(h/ah), cls, 0}
__device__ float4 g_q0[B_ * L_];
__device__ float4 g_q1[B_ * L_];
__device__ float4 g_q2[B_ * L_];
__device__ float  g_partials[NPART];

__global__ void yolo_prologue(const float* __restrict__ gt,
                              const float* __restrict__ anchors)
{
    int t = blockIdx.x * blockDim.x + threadIdx.x;
    if (t >= B_ * L_) return;
    const float* g = gt + (size_t)t * 5;
    float x = g[0], y = g[1], w = g[2], h = g[3], cls = g[4];
    bool valid = w > 0.0f;
    // best anchor by co-centered IoU (scale-invariant; eps effect negligible)
    float best = -1.0f; int k = 0; float aw_k = 1.0f, ah_k = 1.0f;
#pragma unroll
    for (int a = 0; a < 3; a++) {
        float aw = anchors[2 * a], ah = anchors[2 * a + 1];
        float inter = fminf(w, aw) * fminf(h, ah);
        float iou = inter / (w * h + aw * ah - inter + 1e-9f);
        if (iou > best) { best = iou; k = a; aw_k = aw; ah_k = ah; }
    }
    float tw = valid ? logf(w / aw_k) : 0.0f;
    float th = valid ? logf(h / ah_k) : 0.0f;
    g_q0[t] = make_float4(x, y, w * h, __int_as_float(valid ? k : -1));
    g_q1[t] = make_float4(x - 0.5f * w, y - 0.5f * h, x + 0.5f * w, y + 0.5f * h);
    g_q2[t] = make_float4(tw, th, cls, 0.0f);
}

// One warp per (cell, anchor). W == H at every level, which collapses the
// anchor scaling: pred_wh = exp(t)*anchor_base, tw_target = log(w/aw).
template <int W>
__global__ __launch_bounds__(256)
void yolo_main(const float* __restrict__ preds,
               const float* __restrict__ anchors,
               float* __restrict__ out_boxes,
               float* __restrict__ out_scores,
               int lvl_off, int pbase)
{
    constexpr int HW = W * W;
    constexpr int NIDX = HW * 3;
    constexpr float invW = 1.0f / (float)W;
    const float Wf = (float)W;

    __shared__ float4 sq0[L_], sq1[L_], sq2[L_];
    __shared__ float  sred[256];

    int b = blockIdx.y;
    int t = threadIdx.x;
    if (t < L_)            sq0[t]          = g_q0[b * L_ + t];
    else if (t < 2 * L_)   sq1[t - L_]     = g_q1[b * L_ + t - L_];
    else if (t < 3 * L_)   sq2[t - 2 * L_] = g_q2[b * L_ + t - 2 * L_];
    __syncthreads();

    int lane = t & 31;
    int idx  = blockIdx.x * 8 + (t >> 5);   // cell*3 + a
    float local = 0.0f;

    if (idx < NIDX) {
        int cell = idx / 3;
        int a    = idx - cell * 3;
        int ci   = cell / W;
        int cj   = cell - ci * W;
        float cjf = (float)cj, cif = (float)ci;

        const float* f = preds + ((size_t)b * HW + cell) * 255 + a * 85;
        float v0 = f[lane];
        float v1 = f[32 + lane];
        float v2 = (lane < 21) ? f[64 + lane] : -1e30f;

        // ---- softmax over classes (v0 lanes>=5 -> cls lane-5; v1 -> 27+lane; v2 -> 59+lane)
        float cm = fmaxf(v1, v2);
        if (lane >= 5) cm = fmaxf(cm, v0);
#pragma unroll
        for (int o = 16; o; o >>= 1) cm = fmaxf(cm, __shfl_xor_sync(0xFFFFFFFFu, cm, o));
        float e0 = (lane >= 5) ? __expf(v0 - cm) : 0.0f;
        float e1 = __expf(v1 - cm);
        float e2 = (lane < 21) ? __expf(v2 - cm) : 0.0f;
        float es = e0 + e1 + e2;
#pragma unroll
        for (int o = 16; o; o >>= 1) es += __shfl_xor_sync(0xFFFFFFFFu, es, o);
        float inv_es = __fdividef(1.0f, es);

        // ---- warp-scalar slots: lanes 0,1 sigmoid(xy), 2,3 exp(wh), 4 sigmoid(conf)
        bool isexp = (lane == 2) || (lane == 3);
        float xin = isexp ? v0 : -v0;
        float ee  = __expf(xin);
        float sv  = isexp ? ee : __fdividef(1.0f, 1.0f + ee);
        float sx   = __shfl_sync(0xFFFFFFFFu, sv, 0);
        float sy   = __shfl_sync(0xFFFFFFFFu, sv, 1);
        float ew   = __shfl_sync(0xFFFFFFFFu, sv, 2);
        float eh   = __shfl_sync(0xFFFFFFFFu, sv, 3);
        float conf = __shfl_sync(0xFFFFFFFFu, sv, 4);
        float rtw  = __shfl_sync(0xFFFFFFFFu, v0, 2);
        float rth  = __shfl_sync(0xFFFFFFFFu, v0, 3);

        float aw = __ldg(anchors + 2 * a);
        float ah = __ldg(anchors + 2 * a + 1);
        float px = (sx + cjf) * invW;
        float py = (sy + cif) * invW;
        float pw = ew * aw, ph = eh * ah;        // W==H collapse
        float parea = pw * ph;
        float pxm = px - 0.5f * pw, pym = py - 0.5f * ph;
        float pxM = px + 0.5f * pw, pyM = py + 0.5f * ph;

        // ---- scan 50 GT boxes: IoU>0.6 flag (division-free) + mask match
        bool fl0 = false, fl1 = false, m0 = false, m1 = false;
        {
            float4 q0 = sq0[lane]; float4 q1 = sq1[lane];
            float iw = fminf(pxM, q1.z) - fmaxf(pxm, q1.x);
            float ih = fminf(pyM, q1.w) - fmaxf(pym, q1.y);
            float inter = fmaxf(iw, 0.0f) * fmaxf(ih, 0.0f);
            fl0 = inter > 0.375f * (parea + q0.z + 1e-9f);   // iou > 0.6
            float fx = q0.x * Wf - cjf, fy = q0.y * Wf - cif;
            m0 = (__float_as_int(q0.w) == a) && (fx >= 0.0f) && (fx < 1.0f)
                 && (fy >= 0.0f) && (fy < 1.0f);
        }
        if (lane < 18) {
            float4 q0 = sq0[32 + lane]; float4 q1 = sq1[32 + lane];
            float iw = fminf(pxM, q1.z) - fmaxf(pxm, q1.x);
            float ih = fminf(pyM, q1.w) - fmaxf(pym, q1.y);
            float inter = fmaxf(iw, 0.0f) * fmaxf(ih, 0.0f);
            fl1 = inter > 0.375f * (parea + q0.z + 1e-9f);
            float fx = q0.x * Wf - cjf, fy = q0.y * Wf - cif;
            m1 = (__float_as_int(q0.w) == a) && (fx >= 0.0f) && (fx < 1.0f)
                 && (fy >= 0.0f) && (fy < 1.0f);
        }
        unsigned bm0 = __ballot_sync(0xFFFFFFFFu, m0);
        unsigned bm1 = __ballot_sync(0xFFFFFFFFu, m1);
        bool objdet = __any_sync(0xFFFFFFFFu, fl0 || fl1);
        int matched = -1;                       // last (highest l) GT wins
        if (bm1)      matched = 63 - __clz((int)bm1);
        else if (bm0) matched = 31 - __clz((int)bm0);

        // ---- decode outputs
        size_t row = (size_t)b * R_TOT + lvl_off + idx;
        float* sc = out_scores + row * 80;
        float cfi = conf * inv_es;
        if (lane >= 5) sc[lane - 5]  = e0 * cfi;
        sc[27 + lane]               = e1 * cfi;
        if (lane < 21) sc[59 + lane] = e2 * cfi;
        if (lane < 4) {
            float bv = (lane == 0) ? pxm : (lane == 1) ? pym : (lane == 2) ? pxM : pyM;
            out_boxes[row * 4 + lane] = bv * 480.0f;
        }

        // ---- loss terms (raw sums; 0.5 applied in finalize)
        if (matched >= 0) {
            float4 q2 = sq2[matched];
            int clsI = (int)q2.z;
            if (lane >= 5) { float p = e0 * inv_es; float d = ((lane - 5) == clsI ? 1.0f : 0.0f) - p; local += d * d; }
            {                float p = e1 * inv_es; float d = ((27 + lane) == clsI ? 1.0f : 0.0f) - p; local += d * d; }
            if (lane < 21) { float p = e2 * inv_es; float d = ((59 + lane) == clsI ? 1.0f : 0.0f) - p; local += d * d; }
            if (lane == 0) {
                float4 q0m = sq0[matched];
                float dx = (q0m.x * Wf - cjf) - sx;
                float dy = (q0m.y * Wf - cif) - sy;
                float dw = q2.x - rtw;
                float dh = q2.y - rth;
                local += dx * dx + dy * dy + dw * dw + dh * dh;   // COORD=1
                float oc = 1.0f - conf;
                local += 5.0f * oc * oc;                          // OBJ=5
            }
        } else if (lane == 0 && !objdet) {
            local += conf * conf;                                 // NOOBJ=1
        }
    }

    // deterministic block reduction -> one partial per block
    sred[t] = local;
    __syncthreads();
#pragma unroll
    for (int s = 128; s > 0; s >>= 1) {
        if (t < s) sred[t] += sred[t + s];
        __syncthreads();
    }
    if (t == 0)
        g_partials[pbase + blockIdx.y * gridDim.x + blockIdx.x] = sred[0];
}

__global__ void yolo_finalize(float* __restrict__ out, int n)
{
    __shared__ float s[1024];
    float a = 0.0f;
    for (int i = threadIdx.x; i < n; i += 1024) a += g_partials[i];
    s[threadIdx.x] = a;
    __syncthreads();
#pragma unroll
    for (int st = 512; st > 0; st >>= 1) {
        if (threadIdx.x < st) s[threadIdx.x] += s[threadIdx.x + st];
        __syncthreads();
    }
    if (threadIdx.x == 0) out[0] = 0.5f * s[0];
}

extern "C" void kernel_launch(void* const* d_in, const int* in_sizes, int n_in,
                              void* d_out, int out_size)
{
    const float* p0      = (const float*)d_in[0];   // (32,60,60,255)
    const float* p1      = (const float*)d_in[1];   // (32,30,30,255)
    const float* p2      = (const float*)d_in[2];   // (32,15,15,255)
    const float* gt      = (const float*)d_in[3];   // (32,50,5)
    const float* anchors = (const float*)d_in[4];   // (3,2)

    float* out    = (float*)d_out;                  // [0] = loss
    float* boxes  = out + 1;                        // (32,14175,4)
    float* scores = boxes + (size_t)B_ * R_TOT * 4; // (32,14175,80)

    yolo_prologue<<<7, 256>>>(gt, anchors);
    yolo_main<60><<<dim3(1350, 32), 256>>>(p0, anchors, boxes, scores,     0,     0);
    yolo_main<30><<<dim3(338,  32), 256>>>(p1, anchors, boxes, scores, 10800, 43200);
    yolo_main<15><<<dim3(85,   32), 256>>>(p2, anchors, boxes, scores, 13500, 54016);
    yolo_finalize<<<1, 1024>>>(out, NPART);
}